// round 1
// baseline (speedup 1.0000x reference)
#include <cuda_runtime.h>

// IF spiking neuron forward (non-align branch), T=4 timesteps.
// x:       [T*B, 1024, 3072] fp32  (d_in[0])
// thresh2: [1024, 3072] fp32       (d_in[1])
// dtmem:   [1024, 3072] fp32       (d_in[2])
// out:     [T*B, 1024, 3072] fp32
//
// Per feature f and batch b:
//   mem = dtmem[f] * thre[f]
//   for t in 0..T-1:
//     mem += x[t,b,f]
//     spike = (mem >= thre[f]) ? thre[f] : 0
//     out[t,b,f] = spike
//     mem -= spike
//
// HBM-bound: ~830 MB traffic / launch. Vectorized float4, front-batched
// x loads (MLP=4), 2D grid (feature-chunk, batch) -> zero div/mod.

#ifndef T_STEPS
#define T_STEPS 4
#endif

__global__ __launch_bounds__(256) void if_fwd_kernel(
    const float4* __restrict__ x,      // [T, B, N/4]
    const float4* __restrict__ thre,   // [N/4]
    const float4* __restrict__ dtm,    // [N/4]
    float4* __restrict__ out,          // [T, B, N/4]
    long long N4,                      // N/4 (feature count / 4)
    int B)
{
    long long f = (long long)blockIdx.x * blockDim.x + threadIdx.x;
    if (f >= N4) return;
    int b = blockIdx.y;

    float4 th = thre[f];
    float4 dm = dtm[f];

    float4 mem;
    mem.x = dm.x * th.x;
    mem.y = dm.y * th.y;
    mem.z = dm.z * th.z;
    mem.w = dm.w * th.w;

    // Front-batch all T loads: independent of the membrane chain -> MLP=T.
    float4 xv[T_STEPS];
#pragma unroll
    for (int t = 0; t < T_STEPS; t++) {
        xv[t] = x[((long long)t * B + b) * N4 + f];
    }

    float4 sp[T_STEPS];
#pragma unroll
    for (int t = 0; t < T_STEPS; t++) {
        mem.x += xv[t].x;
        mem.y += xv[t].y;
        mem.z += xv[t].z;
        mem.w += xv[t].w;

        float4 s;
        s.x = (mem.x >= th.x) ? th.x : 0.0f;
        s.y = (mem.y >= th.y) ? th.y : 0.0f;
        s.z = (mem.z >= th.z) ? th.z : 0.0f;
        s.w = (mem.w >= th.w) ? th.w : 0.0f;
        sp[t] = s;

        mem.x -= s.x;
        mem.y -= s.y;
        mem.z -= s.z;
        mem.w -= s.w;
    }

#pragma unroll
    for (int t = 0; t < T_STEPS; t++) {
        out[((long long)t * B + b) * N4 + f] = sp[t];
    }
}

extern "C" void kernel_launch(void* const* d_in, const int* in_sizes, int n_in,
                              void* d_out, int out_size)
{
    const float* x   = (const float*)d_in[0];
    const float* th  = (const float*)d_in[1];
    const float* dtm = (const float*)d_in[2];
    float* out = (float*)d_out;

    const long long N = in_sizes[1];            // 1024*3072 = 3145728
    const int B = (int)(in_sizes[0] / (T_STEPS * N)); // 8
    const long long N4 = N / 4;                 // 786432 (divisible by 4)

    const int threads = 256;
    dim3 grid((unsigned)((N4 + threads - 1) / threads), (unsigned)B);

    if_fwd_kernel<<<grid, threads>>>(
        (const float4*)x, (const float4*)th, (const float4*)dtm,
        (float4*)out, N4, B);
}

// round 2
// speedup vs baseline: 1.1662x; 1.1662x over previous
#include <cuda_runtime.h>

// IF spiking neuron forward, T=4. R2: batch loop moved inside the thread so
// thresh2/dtmem are read exactly once per feature (25 MB total instead of
// ~150-200 MB re-fetched across batch waves). Streaming cache hints on the
// x/out traffic keep L2 clean.
//
// x:       [T, B, N] fp32,  thresh2/dtmem: [N] fp32,  out: [T, B, N] fp32
// per (b, f): mem = dtmem*thre; T x { mem+=x; s=(mem>=thre)?thre:0; mem-=s; }

#ifndef T_STEPS
#define T_STEPS 4
#endif

__global__ __launch_bounds__(256) void if_fwd_kernel(
    const float4* __restrict__ x,      // [T, B, N4]
    const float4* __restrict__ thre,   // [N4]
    const float4* __restrict__ dtm,    // [N4]
    float4* __restrict__ out,          // [T, B, N4]
    long long N4,
    int B)
{
    long long f = (long long)blockIdx.x * blockDim.x + threadIdx.x;
    if (f >= N4) return;

    const float4 th = thre[f];
    const float4 dm = dtm[f];

    const float m0x = dm.x * th.x;
    const float m0y = dm.y * th.y;
    const float m0z = dm.z * th.z;
    const float m0w = dm.w * th.w;

#pragma unroll 1
    for (int b = 0; b < B; b++) {
        // Front-batch the T independent loads for this batch (MLP=4).
        float4 xv[T_STEPS];
#pragma unroll
        for (int t = 0; t < T_STEPS; t++) {
            xv[t] = __ldcs(&x[((long long)t * B + b) * N4 + f]);
        }

        float4 mem;
        mem.x = m0x; mem.y = m0y; mem.z = m0z; mem.w = m0w;

        float4 sp[T_STEPS];
#pragma unroll
        for (int t = 0; t < T_STEPS; t++) {
            mem.x += xv[t].x;
            mem.y += xv[t].y;
            mem.z += xv[t].z;
            mem.w += xv[t].w;

            float4 s;
            s.x = (mem.x >= th.x) ? th.x : 0.0f;
            s.y = (mem.y >= th.y) ? th.y : 0.0f;
            s.z = (mem.z >= th.z) ? th.z : 0.0f;
            s.w = (mem.w >= th.w) ? th.w : 0.0f;
            sp[t] = s;

            mem.x -= s.x;
            mem.y -= s.y;
            mem.z -= s.z;
            mem.w -= s.w;
        }

#pragma unroll
        for (int t = 0; t < T_STEPS; t++) {
            __stcs(&out[((long long)t * B + b) * N4 + f], sp[t]);
        }
    }
}

extern "C" void kernel_launch(void* const* d_in, const int* in_sizes, int n_in,
                              void* d_out, int out_size)
{
    const float* x   = (const float*)d_in[0];
    const float* th  = (const float*)d_in[1];
    const float* dtm = (const float*)d_in[2];
    float* out = (float*)d_out;

    const long long N = in_sizes[1];                   // 1024*3072
    const int B = (int)(in_sizes[0] / (T_STEPS * N));  // 8
    const long long N4 = N / 4;

    const int threads = 256;
    dim3 grid((unsigned)((N4 + threads - 1) / threads));

    if_fwd_kernel<<<grid, threads>>>(
        (const float4*)x, (const float4*)th, (const float4*)dtm,
        (float4*)out, N4, B);
}

// round 3
// speedup vs baseline: 1.1686x; 1.0020x over previous
#include <cuda_runtime.h>

// IF spiking neuron forward, T=4. R3: software-pipelined batch loop
// (prefetch batch b+1's loads before compute/store of batch b -> MLP=8),
// 128-thread blocks for finer wave scheduling. Params still read once per
// feature (minimal DRAM traffic ~830 MB).

#ifndef T_STEPS
#define T_STEPS 4
#endif

__global__ __launch_bounds__(128) void if_fwd_kernel(
    const float4* __restrict__ x,      // [T, B, N4]
    const float4* __restrict__ thre,   // [N4]
    const float4* __restrict__ dtm,    // [N4]
    float4* __restrict__ out,          // [T, B, N4]
    long long N4,
    int B)
{
    long long f = (long long)blockIdx.x * blockDim.x + threadIdx.x;
    if (f >= N4) return;

    const float4 th = thre[f];
    float4 dm = dtm[f];
    // initial membrane (reuses dm registers)
    dm.x *= th.x; dm.y *= th.y; dm.z *= th.z; dm.w *= th.w;

    const float4* xp = x + f;
    float4* op = out + f;
    const long long tstride = (long long)B * N4;

    // Prologue: loads for batch 0
    float4 xv[T_STEPS];
#pragma unroll
    for (int t = 0; t < T_STEPS; t++)
        xv[t] = __ldcs(xp + (long long)t * tstride);

#pragma unroll 1
    for (int b = 0; b < B; b++) {
        // Prefetch next batch's loads before touching this batch's compute.
        float4 xn[T_STEPS];
        if (b + 1 < B) {
#pragma unroll
            for (int t = 0; t < T_STEPS; t++)
                xn[t] = __ldcs(xp + (long long)t * tstride + (b + 1) * N4);
        }

        float4 mem = dm;
        float4 sp[T_STEPS];
#pragma unroll
        for (int t = 0; t < T_STEPS; t++) {
            mem.x += xv[t].x;
            mem.y += xv[t].y;
            mem.z += xv[t].z;
            mem.w += xv[t].w;

            float4 s;
            s.x = (mem.x >= th.x) ? th.x : 0.0f;
            s.y = (mem.y >= th.y) ? th.y : 0.0f;
            s.z = (mem.z >= th.z) ? th.z : 0.0f;
            s.w = (mem.w >= th.w) ? th.w : 0.0f;
            sp[t] = s;

            mem.x -= s.x;
            mem.y -= s.y;
            mem.z -= s.z;
            mem.w -= s.w;
        }

#pragma unroll
        for (int t = 0; t < T_STEPS; t++)
            __stcs(op + (long long)t * tstride + b * N4, sp[t]);

#pragma unroll
        for (int t = 0; t < T_STEPS; t++)
            xv[t] = xn[t];
    }
}

extern "C" void kernel_launch(void* const* d_in, const int* in_sizes, int n_in,
                              void* d_out, int out_size)
{
    const float* x   = (const float*)d_in[0];
    const float* th  = (const float*)d_in[1];
    const float* dtm = (const float*)d_in[2];
    float* out = (float*)d_out;

    const long long N = in_sizes[1];                   // 1024*3072
    const int B = (int)(in_sizes[0] / (T_STEPS * N));  // 8
    const long long N4 = N / 4;

    const int threads = 128;
    dim3 grid((unsigned)((N4 + threads - 1) / threads));

    if_fwd_kernel<<<grid, threads>>>(
        (const float4*)x, (const float4*)th, (const float4*)dtm,
        (float4*)out, N4, B);
}